// round 15
// baseline (speedup 1.0000x reference)
#include <cuda_runtime.h>
#include <math.h>

#define N_IMG 4
#define CIN 512
#define COUT 512
#define HW 2500
#define KDIM (CIN*9)
#define R_TOT 22500
#define NSORT 32768
#define NPROP 6000
#define NKEEP 300

// output region offsets (floats)
#define O_LOC   0
#define O_SCORE 360000
#define O_ROIS  540000
#define O_RIDX  544800
#define O_ANCH  546000

extern "C" __device__ float __nv_expf(float);

// ---------------- scratch (static device arrays; no allocation) ----------------
__device__ __align__(16) float g_inter[N_IMG*COUT*HW];     // 20.48 MB
__device__ __align__(16) float g_wh[64*512];               // packed head weights
__device__ float g_bh[64];
__device__ __align__(16) float4 g_roi[N_IMG*R_TOT];        // clipped boxes
__device__ unsigned long long g_keys[N_IMG*NSORT];         // sort keys

// ---------------- prepack head weights ----------------
__global__ __launch_bounds__(256) void prepack_kernel(
        const float* __restrict__ w_score, const float* __restrict__ b_score,
        const float* __restrict__ w_loc,   const float* __restrict__ b_loc) {
    int i = blockIdx.x * blockDim.x + threadIdx.x;
    if (i < 64*512) {
        int o = i >> 9, c = i & 511;
        float v = 0.f;
        if (o < 36)      v = w_loc[o*512 + c];
        else if (o < 54) v = w_score[(o-36)*512 + c];
        g_wh[i] = v;
    }
    if (i < 64) {
        float v = 0.f;
        if (i < 36)      v = b_loc[i];
        else if (i < 54) v = b_score[i-36];
        g_bh[i] = v;
    }
}

// 8-lane pairwise-tree combine (DO NOT CHANGE — bit-exact contract with reference)
__device__ __forceinline__ float tree8(const float* l) {
    float s01 = __fadd_rn(l[0], l[1]);
    float s23 = __fadd_rn(l[2], l[3]);
    float s45 = __fadd_rn(l[4], l[5]);
    float s67 = __fadd_rn(l[6], l[7]);
    float a = __fadd_rn(s01, s23);
    float b = __fadd_rn(s45, s67);
    return __fadd_rn(a, b);
}

// ---------------- conv3x3 + bias + relu (implicit GEMM, 8-lane accumulation) ----------------
// BIT-EXACT CONTRACT: per output, k = c*9 + off ascending, lane = k & 7,
// __fmaf_rn chain per lane, tree8 combine, __fadd_rn bias, relu.
// Tile 64(M) x 32(P), 128 threads, microtile 4x4 x 8 lanes (2 B/FMA smem),
// double-buffered, K-tile 16. 3 CTAs/SM (12 warps — stall slack).
// grid: (79, 8, 4), block 128
__global__ __launch_bounds__(128, 3) void conv3x3_kernel(
        const float* __restrict__ x, const float* __restrict__ w,
        const float* __restrict__ bias) {
    const int n = blockIdx.z, mt = blockIdx.y, pt = blockIdx.x;
    const int tid = threadIdx.x;
    const int tx = tid & 7, ty = tid >> 3;     // tx 0..7 (p), ty 0..15 (m)
    __shared__ float As[2][16][68];
    __shared__ float Bs[2][16][36];
    const int m0 = mt * 64, p0 = pt * 32;
    float acc[4][4][8];
#pragma unroll
    for (int i = 0; i < 4; i++)
#pragma unroll
        for (int j = 0; j < 4; j++)
#pragma unroll
            for (int u = 0; u < 8; u++) acc[i][j][u] = 0.f;

    const float* xn = x + (size_t)n * CIN * HW;
    // A loader: 8 k per thread (two float4): row am, k base ak
    const int am = tid >> 1;          // 0..63
    const int ak = (tid & 1) * 8;     // 0 or 8
    // B loader: 4 p per thread, 1 k row
    const int bk = tid >> 3;          // 0..15
    const int bp = (tid & 7) * 4;     // 0..28
    const int pg0 = p0 + bp;

    const float* wrow = w + (size_t)(m0 + am) * KDIM;

    // ---- prologue: tile kt=0 into buffer 0 ----
    {
        float4 av0 = *(const float4*)(wrow + ak);
        float4 av1 = *(const float4*)(wrow + ak + 4);
        As[0][ak+0][am] = av0.x; As[0][ak+1][am] = av0.y;
        As[0][ak+2][am] = av0.z; As[0][ak+3][am] = av0.w;
        As[0][ak+4][am] = av1.x; As[0][ak+5][am] = av1.y;
        As[0][ak+6][am] = av1.z; As[0][ak+7][am] = av1.w;
        int k = bk;
        int c = k / 9;
        int off = k - c * 9;
        int dy = off / 3 - 1, dx = off - (off/3)*3 - 1;
        const float* xc = xn + (size_t)c * HW;
#pragma unroll
        for (int j = 0; j < 4; j++) {
            int p = pg0 + j;
            float v = 0.f;
            if (p < HW) {
                int yy = p / 50 + dy, xx = p - (p/50)*50 + dx;
                if ((unsigned)yy < 50u && (unsigned)xx < 50u) v = xc[yy*50 + xx];
            }
            Bs[0][bk][bp + j] = v;
        }
    }
    __syncthreads();

    int cur = 0;
    for (int kt = 0; kt < KDIM; kt += 16) {
        const bool has = (kt + 16) < KDIM;
        float4 av0, av1;
        float bb[4];
        if (has) {
            const float* wn = wrow + kt + 16;
            av0 = *(const float4*)(wn + ak);
            av1 = *(const float4*)(wn + ak + 4);
            int k = kt + 16 + bk;
            int c = k / 9;
            int off = k - c * 9;
            int dy = off / 3 - 1, dx = off - (off/3)*3 - 1;
            const float* xc = xn + (size_t)c * HW;
#pragma unroll
            for (int j = 0; j < 4; j++) {
                bb[j] = 0.f;
                int p = pg0 + j;
                if (p < HW) {
                    int yy = p / 50 + dy, xx = p - (p/50)*50 + dx;
                    if ((unsigned)yy < 50u && (unsigned)xx < 50u) bb[j] = xc[yy*50 + xx];
                }
            }
        }
        // compute on buffer cur — IDENTICAL per-output operand order
#pragma unroll
        for (int kk = 0; kk < 16; kk++) {
            float4 a4 = *(const float4*)&As[cur][kk][ty*4];
            float4 b4 = *(const float4*)&Bs[cur][kk][tx*4];
            float ar[4] = {a4.x, a4.y, a4.z, a4.w};
            float br[4] = {b4.x, b4.y, b4.z, b4.w};
            int lane = kk & 7;
#pragma unroll
            for (int i = 0; i < 4; i++)
#pragma unroll
                for (int j = 0; j < 4; j++)
                    acc[i][j][lane] = __fmaf_rn(ar[i], br[j], acc[i][j][lane]);
        }
        if (has) {
            int nxt = cur ^ 1;
            As[nxt][ak+0][am] = av0.x; As[nxt][ak+1][am] = av0.y;
            As[nxt][ak+2][am] = av0.z; As[nxt][ak+3][am] = av0.w;
            As[nxt][ak+4][am] = av1.x; As[nxt][ak+5][am] = av1.y;
            As[nxt][ak+6][am] = av1.z; As[nxt][ak+7][am] = av1.w;
            Bs[nxt][bk][bp+0] = bb[0];
            Bs[nxt][bk][bp+1] = bb[1];
            Bs[nxt][bk][bp+2] = bb[2];
            Bs[nxt][bk][bp+3] = bb[3];
            __syncthreads();
            cur = nxt;
        }
    }

    float* on = g_inter + (size_t)n * COUT * HW;
#pragma unroll
    for (int i = 0; i < 4; i++) {
        int m = m0 + ty*4 + i;
        float bv = bias[m];
#pragma unroll
        for (int j = 0; j < 4; j++) {
            int p = p0 + tx*4 + j;
            if (p < HW) {
                float v = __fadd_rn(tree8(acc[i][j]), bv);
                on[(size_t)m * HW + p] = v > 0.f ? v : 0.f;
            }
        }
    }
}

// ---------------- 1x1 heads GEMM (64 packed outs x 512, 8-lane accumulation) ----------------
// grid: (79, 1, 4), block 256; tile 64(M) x 32(P), microtile 4x2
__global__ __launch_bounds__(256) void heads_kernel(float* __restrict__ out) {
    const int n = blockIdx.z, pt = blockIdx.x;
    const int tid = threadIdx.x;
    const int tx = tid & 15, ty = tid >> 4;
    __shared__ float As[16][68];
    __shared__ float Bs[16][36];
    const int p0 = pt * 32;
    float acc[4][2][8];
#pragma unroll
    for (int i = 0; i < 4; i++)
#pragma unroll
        for (int j = 0; j < 2; j++)
#pragma unroll
            for (int u = 0; u < 8; u++) acc[i][j][u] = 0.f;

    const float* bn = g_inter + (size_t)n * CIN * HW;
    const int am = tid >> 2, ak = (tid & 3) * 4;
    const int bk = tid >> 4, bp = (tid & 15) * 2;

    for (int kt = 0; kt < 512; kt += 16) {
        float4 av = *(const float4*)(g_wh + (size_t)am * 512 + kt + ak);
        As[ak+0][am] = av.x; As[ak+1][am] = av.y; As[ak+2][am] = av.z; As[ak+3][am] = av.w;
        const float* brow = bn + (size_t)(kt + bk) * HW;
#pragma unroll
        for (int j = 0; j < 2; j++) {
            int p = p0 + bp + j;
            Bs[bk][bp + j] = (p < HW) ? brow[p] : 0.f;
        }
        __syncthreads();
#pragma unroll
        for (int kk = 0; kk < 16; kk++) {
            float4 a4 = *(const float4*)&As[kk][ty*4];
            float b0 = Bs[kk][tx*2], b1 = Bs[kk][tx*2+1];
            float ar[4] = {a4.x, a4.y, a4.z, a4.w};
            int lane = kk & 7;
#pragma unroll
            for (int i = 0; i < 4; i++) {
                acc[i][0][lane] = __fmaf_rn(ar[i], b0, acc[i][0][lane]);
                acc[i][1][lane] = __fmaf_rn(ar[i], b1, acc[i][1][lane]);
            }
        }
        __syncthreads();
    }

#pragma unroll
    for (int i = 0; i < 4; i++) {
        int o = ty*4 + i;
        float bv = g_bh[o];
#pragma unroll
        for (int j = 0; j < 2; j++) {
            int p = p0 + tx*2 + j;
            if (p < HW) {
                float v = __fadd_rn(tree8(acc[i][j]), bv);
                if (o < 36)       out[O_LOC   + (size_t)n*90000 + (size_t)p*36 + o] = v;
                else if (o < 54)  out[O_SCORE + (size_t)n*45000 + (size_t)p*18 + (o-36)] = v;
            }
        }
    }
}

// ---------------- decode: softmax fg, anchors, loc2box, clip, keys ----------------
__global__ __launch_bounds__(256) void decode_kernel(
        float* __restrict__ out, const int* __restrict__ p_h, const int* __restrict__ p_w) {
    int g = blockIdx.x * blockDim.x + threadIdx.x;
    if (g >= N_IMG * NSORT) return;
    int n = g >> 15;
    int r = g & (NSORT - 1);
    if (r >= R_TOT) { g_keys[g] = ~0ULL; return; }

    int p = r / 9, a = r - (r/9)*9;
    const float* sc = out + O_SCORE + (size_t)n*45000 + (size_t)p*18 + 2*a;
    float s0 = sc[0], s1 = sc[1];
    float mx = fmaxf(s0, s1);
    float e0 = __nv_expf(__fsub_rn(s0, mx));
    float e1 = __nv_expf(__fsub_rn(s1, mx));
    float fg = __fdiv_rn(e1, __fadd_rn(e0, e1));

    int ridx = a / 3, sidx = a - ridx*3;
    double rr = (ridx == 0) ? 0.5 : ((ridx == 1) ? 1.0 : 2.0);
    double ss = (sidx == 0) ? 8.0 : ((sidx == 1) ? 16.0 : 32.0);
    double hh = (16.0 * sqrt(rr)) * ss;
    double wwd = (16.0 * sqrt(1.0 / rr)) * ss;
    float base0 = (float)(8.0 - hh * 0.5);
    float base1 = (float)(8.0 - wwd * 0.5);
    float base2 = (float)(8.0 + hh * 0.5);
    float base3 = (float)(8.0 + wwd * 0.5);
    int py = p / 50, px = p - (p/50)*50;
    double shy = (double)(16 * py);
    double shx = (double)(16 * px);
    float a0 = (float)(shy + (double)base0);
    float a1 = (float)(shx + (double)base1);
    float a2 = (float)(shy + (double)base2);
    float a3 = (float)(shx + (double)base3);
    if (n == 0) {
        float* ao = out + O_ANCH + (size_t)r * 4;
        ao[0] = a0; ao[1] = a1; ao[2] = a2; ao[3] = a3;
    }

    const float* lp = out + O_LOC + (size_t)n*90000 + (size_t)p*36 + a*4;
    float l0 = lp[0], l1 = lp[1], l2 = lp[2], l3 = lp[3];
    float ah = __fsub_rn(a2, a0);
    float aw = __fsub_rn(a3, a1);
    float acy = __fadd_rn(a0, __fmul_rn(0.5f, ah));
    float acx = __fadd_rn(a1, __fmul_rn(0.5f, aw));
    float bcy = __fadd_rn(__fmul_rn(l0, ah), acy);
    float bcx = __fadd_rn(__fmul_rn(l1, aw), acx);
    float bh = __fmul_rn(__nv_expf(l2), ah);
    float bw = __fmul_rn(__nv_expf(l3), aw);
    float y1 = __fsub_rn(bcy, __fmul_rn(0.5f, bh));
    float x1 = __fsub_rn(bcx, __fmul_rn(0.5f, bw));
    float y2 = __fadd_rn(bcy, __fmul_rn(0.5f, bh));
    float x2 = __fadd_rn(bcx, __fmul_rn(0.5f, bw));
    float H = (float)(*p_h), W = (float)(*p_w);
    y1 = fminf(fmaxf(y1, 0.f), H); x1 = fminf(fmaxf(x1, 0.f), W);
    y2 = fminf(fmaxf(y2, 0.f), H); x2 = fminf(fmaxf(x2, 0.f), W);
    bool valid = (__fsub_rn(y2, y1) >= 16.0f) && (__fsub_rn(x2, x1) >= 16.0f);
    float score = valid ? fg : -INFINITY;

    g_roi[(size_t)n * R_TOT + r] = make_float4(y1, x1, y2, x2);

    unsigned ub = __float_as_uint(score);
    unsigned s = (ub & 0x80000000u) ? ~ub : (ub | 0x80000000u);
    g_keys[g] = ((unsigned long long)(~s) << 32) | (unsigned)r;
}

// ---------------- bitonic sort ----------------
__device__ __forceinline__ void cmpswap(unsigned long long& a, unsigned long long& b, bool up) {
    bool sw = up ? (a > b) : (a < b);
    if (sw) { unsigned long long t = a; a = b; b = t; }
}

__global__ __launch_bounds__(1024, 1) void bitonic_local_kernel() {
    __shared__ unsigned long long sk[2048];
    int n = blockIdx.x >> 4;
    int chunk = blockIdx.x & 15;
    int base = n * NSORT + chunk * 2048;
    int t = threadIdx.x;
    sk[t] = g_keys[base + t];
    sk[t + 1024] = g_keys[base + t + 1024];
    __syncthreads();
    int gb = chunk * 2048;
    for (int k = 2; k <= 2048; k <<= 1) {
        for (int j = k >> 1; j > 0; j >>= 1) {
            int lo = ((t & ~(j - 1)) << 1) | (t & (j - 1));
            int hi = lo + j;
            bool up = (((gb + lo) & k) == 0);
            cmpswap(sk[lo], sk[hi], up);
            __syncthreads();
        }
    }
    g_keys[base + t] = sk[t];
    g_keys[base + t + 1024] = sk[t + 1024];
}

__global__ __launch_bounds__(256) void bitonic_global_kernel(int k, int j) {
    int g = blockIdx.x * blockDim.x + threadIdx.x;
    int n = g >> 14;
    int i = g & 16383;
    int lo = ((i & ~(j - 1)) << 1) | (i & (j - 1));
    int hi = lo + j;
    bool up = ((lo & k) == 0);
    unsigned long long* kp = g_keys + (size_t)n * NSORT;
    unsigned long long a = kp[lo], b = kp[hi];
    bool sw = up ? (a > b) : (a < b);
    if (sw) { kp[lo] = b; kp[hi] = a; }
}

__global__ __launch_bounds__(1024, 1) void bitonic_merge_kernel(int k) {
    __shared__ unsigned long long sk[2048];
    int n = blockIdx.x >> 4;
    int chunk = blockIdx.x & 15;
    int base = n * NSORT + chunk * 2048;
    int t = threadIdx.x;
    sk[t] = g_keys[base + t];
    sk[t + 1024] = g_keys[base + t + 1024];
    __syncthreads();
    bool up = (((chunk * 2048) & k) == 0);
    for (int j = 1024; j > 0; j >>= 1) {
        int lo = ((t & ~(j - 1)) << 1) | (t & (j - 1));
        int hi = lo + j;
        cmpswap(sk[lo], sk[hi], up);
        __syncthreads();
    }
    g_keys[base + t] = sk[t];
    g_keys[base + t + 1024] = sk[t + 1024];
}

// ---------------- NMS ----------------
#define NMS_SMEM (NPROP*16 + NKEEP*5*4 + NPROP)

__global__ __launch_bounds__(128) void nms_kernel(float* __restrict__ out) {
    extern __shared__ char smem[];
    float4* sbox = (float4*)smem;
    float* skept = (float*)(smem + NPROP * 16);
    unsigned char* sfin = (unsigned char*)(smem + NPROP * 16 + NKEEP * 5 * 4);
    __shared__ int s_count;

    int n = blockIdx.x;
    int t = threadIdx.x;

    for (int r = t; r < NPROP; r += blockDim.x) {
        unsigned long long key = g_keys[(size_t)n * NSORT + r];
        unsigned idx = (unsigned)key;
        sbox[r] = g_roi[(size_t)n * R_TOT + idx];
        sfin[r] = ((unsigned)(key >> 32) != 0xFF800000u) ? 1 : 0;
    }
    __syncthreads();

    if (t < 32) {
        int count = 0;
        for (int i = 0; i < NPROP && count < NKEEP; i++) {
            if (!sfin[i]) continue;
            float4 bi = sbox[i];
            float areai = __fmul_rn(__fsub_rn(bi.z, bi.x), __fsub_rn(bi.w, bi.y));
            bool sup = false;
            for (int g0 = 0; g0 < count; g0 += 32) {
                int kk = g0 + t;
                bool pr = false;
                if (kk < count) {
                    const float* kb = &skept[kk * 5];
                    float ty_ = fmaxf(bi.x, kb[0]);
                    float tx_ = fmaxf(bi.y, kb[1]);
                    float by_ = fminf(bi.z, kb[2]);
                    float bx_ = fminf(bi.w, kb[3]);
                    float ih = fmaxf(__fsub_rn(by_, ty_), 0.f);
                    float iw = fmaxf(__fsub_rn(bx_, tx_), 0.f);
                    float inter = __fmul_rn(ih, iw);
                    float denom = __fadd_rn(__fsub_rn(__fadd_rn(areai, kb[4]), inter), 1e-9f);
                    float iou = __fdiv_rn(inter, denom);
                    pr = iou > 0.7f;
                }
                if (__ballot_sync(0xFFFFFFFFu, pr)) { sup = true; break; }
            }
            if (!sup) {
                if (t == 0) {
                    float* kb = &skept[count * 5];
                    kb[0] = bi.x; kb[1] = bi.y; kb[2] = bi.z; kb[3] = bi.w; kb[4] = areai;
                    float* o = out + O_ROIS + ((size_t)n * NKEEP + count) * 4;
                    o[0] = bi.x; o[1] = bi.y; o[2] = bi.z; o[3] = bi.w;
                }
                count++;
                __syncwarp();
            }
        }
        if (t == 0) s_count = count;
    }
    __syncthreads();
    int cnt = s_count;
    for (int r = t; r < NKEEP; r += blockDim.x) {
        if (r >= cnt) {
            float* o = out + O_ROIS + ((size_t)n * NKEEP + r) * 4;
            o[0] = 0.f; o[1] = 0.f; o[2] = 0.f; o[3] = 0.f;
        }
        out[O_RIDX + (size_t)n * NKEEP + r] = (float)n;
    }
}

// ---------------- launch (single stream) ----------------
extern "C" void kernel_launch(void* const* d_in, const int* in_sizes, int n_in,
                              void* d_out, int out_size) {
    const float* x       = (const float*)d_in[0];
    const float* w1      = (const float*)d_in[1];
    const float* b1      = (const float*)d_in[2];
    const float* w_score = (const float*)d_in[3];
    const float* b_score = (const float*)d_in[4];
    const float* w_loc   = (const float*)d_in[5];
    const float* b_loc   = (const float*)d_in[6];
    const int*   p_h     = (const int*)d_in[7];
    const int*   p_w     = (const int*)d_in[8];
    float* out = (float*)d_out;

    static int smem_set = 0;
    if (!smem_set) {
        cudaFuncSetAttribute(nms_kernel, cudaFuncAttributeMaxDynamicSharedMemorySize, NMS_SMEM);
        smem_set = 1;
    }

    prepack_kernel<<<(64*512 + 255)/256, 256>>>(w_score, b_score, w_loc, b_loc);

    dim3 gconv(79, 8, N_IMG);
    conv3x3_kernel<<<gconv, 128>>>(x, w1, b1);

    dim3 ghead(79, 1, N_IMG);
    heads_kernel<<<ghead, 256>>>(out);

    decode_kernel<<<(N_IMG * NSORT + 255)/256, 256>>>(out, p_h, p_w);

    bitonic_local_kernel<<<64, 1024>>>();
    for (int k = 4096; k <= NSORT; k <<= 1) {
        for (int j = k >> 1; j >= 2048; j >>= 1)
            bitonic_global_kernel<<<256, 256>>>(k, j);
        bitonic_merge_kernel<<<64, 1024>>>(k);
    }

    nms_kernel<<<N_IMG, 128, NMS_SMEM>>>(out);
}

// round 16
// speedup vs baseline: 1.0472x; 1.0472x over previous
#include <cuda_runtime.h>
#include <math.h>

#define N_IMG 4
#define CIN 512
#define COUT 512
#define HW 2500
#define KDIM (CIN*9)
#define R_TOT 22500
#define NSORT 32768
#define NPROP 6000
#define NKEEP 300

// output region offsets (floats)
#define O_LOC   0
#define O_SCORE 360000
#define O_ROIS  540000
#define O_RIDX  544800
#define O_ANCH  546000

extern "C" __device__ float __nv_expf(float);

// ---------------- scratch (static device arrays; no allocation) ----------------
__device__ __align__(16) float g_inter[N_IMG*COUT*HW];     // 20.48 MB
__device__ __align__(16) float g_wh[64*512];               // packed head weights
__device__ float g_bh[64];
__device__ __align__(16) float4 g_roi[N_IMG*R_TOT];        // clipped boxes
__device__ unsigned long long g_keys[N_IMG*NSORT];         // sort keys

// ---------------- prepack head weights ----------------
__global__ __launch_bounds__(256) void prepack_kernel(
        const float* __restrict__ w_score, const float* __restrict__ b_score,
        const float* __restrict__ w_loc,   const float* __restrict__ b_loc) {
    int i = blockIdx.x * blockDim.x + threadIdx.x;
    if (i < 64*512) {
        int o = i >> 9, c = i & 511;
        float v = 0.f;
        if (o < 36)      v = w_loc[o*512 + c];
        else if (o < 54) v = w_score[(o-36)*512 + c];
        g_wh[i] = v;
    }
    if (i < 64) {
        float v = 0.f;
        if (i < 36)      v = b_loc[i];
        else if (i < 54) v = b_score[i-36];
        g_bh[i] = v;
    }
}

// 8-lane pairwise-tree combine (DO NOT CHANGE — bit-exact contract with reference)
__device__ __forceinline__ float tree8(const float* l) {
    float s01 = __fadd_rn(l[0], l[1]);
    float s23 = __fadd_rn(l[2], l[3]);
    float s45 = __fadd_rn(l[4], l[5]);
    float s67 = __fadd_rn(l[6], l[7]);
    float a = __fadd_rn(s01, s23);
    float b = __fadd_rn(s45, s67);
    return __fadd_rn(a, b);
}

// ---------------- conv3x3 + bias + relu (implicit GEMM, 8-lane accumulation) ----------------
// BIT-EXACT CONTRACT: per output, k = c*9 + off ascending, lane = k & 7,
// __fmaf_rn chain per lane, tree8 combine, __fadd_rn bias, relu.
// R14-proven config: tile 64(M) x 32(P), 128 threads, microtile 4x4 x 8 lanes,
// double-buffered, K-tile 16, 2 CTAs/SM.
// grid: (79, 8, 4), block 128
__global__ __launch_bounds__(128, 2) void conv3x3_kernel(
        const float* __restrict__ x, const float* __restrict__ w,
        const float* __restrict__ bias) {
    const int n = blockIdx.z, mt = blockIdx.y, pt = blockIdx.x;
    const int tid = threadIdx.x;
    const int tx = tid & 7, ty = tid >> 3;     // tx 0..7 (p), ty 0..15 (m)
    __shared__ float As[2][16][68];
    __shared__ float Bs[2][16][36];
    const int m0 = mt * 64, p0 = pt * 32;
    float acc[4][4][8];
#pragma unroll
    for (int i = 0; i < 4; i++)
#pragma unroll
        for (int j = 0; j < 4; j++)
#pragma unroll
            for (int u = 0; u < 8; u++) acc[i][j][u] = 0.f;

    const float* xn = x + (size_t)n * CIN * HW;
    // A loader: 8 k per thread (two float4): row am, k base ak
    const int am = tid >> 1;          // 0..63
    const int ak = (tid & 1) * 8;     // 0 or 8
    // B loader: 4 p per thread, 1 k row
    const int bk = tid >> 3;          // 0..15
    const int bp = (tid & 7) * 4;     // 0..28
    const int pg0 = p0 + bp;

    const float* wrow = w + (size_t)(m0 + am) * KDIM;

    // ---- prologue: tile kt=0 into buffer 0 ----
    {
        float4 av0 = *(const float4*)(wrow + ak);
        float4 av1 = *(const float4*)(wrow + ak + 4);
        As[0][ak+0][am] = av0.x; As[0][ak+1][am] = av0.y;
        As[0][ak+2][am] = av0.z; As[0][ak+3][am] = av0.w;
        As[0][ak+4][am] = av1.x; As[0][ak+5][am] = av1.y;
        As[0][ak+6][am] = av1.z; As[0][ak+7][am] = av1.w;
        int k = bk;
        int c = k / 9;
        int off = k - c * 9;
        int dy = off / 3 - 1, dx = off - (off/3)*3 - 1;
        const float* xc = xn + (size_t)c * HW;
#pragma unroll
        for (int j = 0; j < 4; j++) {
            int p = pg0 + j;
            float v = 0.f;
            if (p < HW) {
                int yy = p / 50 + dy, xx = p - (p/50)*50 + dx;
                if ((unsigned)yy < 50u && (unsigned)xx < 50u) v = xc[yy*50 + xx];
            }
            Bs[0][bk][bp + j] = v;
        }
    }
    __syncthreads();

    int cur = 0;
    for (int kt = 0; kt < KDIM; kt += 16) {
        const bool has = (kt + 16) < KDIM;
        float4 av0, av1;
        float bb[4];
        if (has) {
            const float* wn = wrow + kt + 16;
            av0 = *(const float4*)(wn + ak);
            av1 = *(const float4*)(wn + ak + 4);
            int k = kt + 16 + bk;
            int c = k / 9;
            int off = k - c * 9;
            int dy = off / 3 - 1, dx = off - (off/3)*3 - 1;
            const float* xc = xn + (size_t)c * HW;
#pragma unroll
            for (int j = 0; j < 4; j++) {
                bb[j] = 0.f;
                int p = pg0 + j;
                if (p < HW) {
                    int yy = p / 50 + dy, xx = p - (p/50)*50 + dx;
                    if ((unsigned)yy < 50u && (unsigned)xx < 50u) bb[j] = xc[yy*50 + xx];
                }
            }
        }
        // compute on buffer cur — IDENTICAL per-output operand order
#pragma unroll
        for (int kk = 0; kk < 16; kk++) {
            float4 a4 = *(const float4*)&As[cur][kk][ty*4];
            float4 b4 = *(const float4*)&Bs[cur][kk][tx*4];
            float ar[4] = {a4.x, a4.y, a4.z, a4.w};
            float br[4] = {b4.x, b4.y, b4.z, b4.w};
            int lane = kk & 7;
#pragma unroll
            for (int i = 0; i < 4; i++)
#pragma unroll
                for (int j = 0; j < 4; j++)
                    acc[i][j][lane] = __fmaf_rn(ar[i], br[j], acc[i][j][lane]);
        }
        if (has) {
            int nxt = cur ^ 1;
            As[nxt][ak+0][am] = av0.x; As[nxt][ak+1][am] = av0.y;
            As[nxt][ak+2][am] = av0.z; As[nxt][ak+3][am] = av0.w;
            As[nxt][ak+4][am] = av1.x; As[nxt][ak+5][am] = av1.y;
            As[nxt][ak+6][am] = av1.z; As[nxt][ak+7][am] = av1.w;
            Bs[nxt][bk][bp+0] = bb[0];
            Bs[nxt][bk][bp+1] = bb[1];
            Bs[nxt][bk][bp+2] = bb[2];
            Bs[nxt][bk][bp+3] = bb[3];
            __syncthreads();
            cur = nxt;
        }
    }

    float* on = g_inter + (size_t)n * COUT * HW;
#pragma unroll
    for (int i = 0; i < 4; i++) {
        int m = m0 + ty*4 + i;
        float bv = bias[m];
#pragma unroll
        for (int j = 0; j < 4; j++) {
            int p = p0 + tx*4 + j;
            if (p < HW) {
                float v = __fadd_rn(tree8(acc[i][j]), bv);
                on[(size_t)m * HW + p] = v > 0.f ? v : 0.f;
            }
        }
    }
}

// ---------------- 1x1 heads GEMM (64 packed outs x 512, 8-lane accumulation) ----------------
// Double-buffered (R11 pattern), identical compute order. grid: (79, 1, 4), block 256
__global__ __launch_bounds__(256, 2) void heads_kernel(float* __restrict__ out) {
    const int n = blockIdx.z, pt = blockIdx.x;
    const int tid = threadIdx.x;
    const int tx = tid & 15, ty = tid >> 4;
    __shared__ float As[2][16][68];
    __shared__ float Bs[2][16][36];
    const int p0 = pt * 32;
    float acc[4][2][8];
#pragma unroll
    for (int i = 0; i < 4; i++)
#pragma unroll
        for (int j = 0; j < 2; j++)
#pragma unroll
            for (int u = 0; u < 8; u++) acc[i][j][u] = 0.f;

    const float* bn = g_inter + (size_t)n * CIN * HW;
    const int am = tid >> 2, ak = (tid & 3) * 4;
    const int bk = tid >> 4, bp = (tid & 15) * 2;
    const int pgA = p0 + bp, pgB = p0 + bp + 1;
    const bool pvA = pgA < HW, pvB = pgB < HW;

    // prologue: kt=0
    {
        float4 av = *(const float4*)(g_wh + (size_t)am * 512 + ak);
        As[0][ak+0][am] = av.x; As[0][ak+1][am] = av.y;
        As[0][ak+2][am] = av.z; As[0][ak+3][am] = av.w;
        const float* brow = bn + (size_t)bk * HW;
        Bs[0][bk][bp + 0] = pvA ? brow[pgA] : 0.f;
        Bs[0][bk][bp + 1] = pvB ? brow[pgB] : 0.f;
    }
    __syncthreads();

    int cur = 0;
    for (int kt = 0; kt < 512; kt += 16) {
        const bool has = (kt + 16) < 512;
        float4 av;
        float bb0 = 0.f, bb1 = 0.f;
        if (has) {
            av = *(const float4*)(g_wh + (size_t)am * 512 + (kt + 16) + ak);
            const float* brow = bn + (size_t)(kt + 16 + bk) * HW;
            if (pvA) bb0 = brow[pgA];
            if (pvB) bb1 = brow[pgB];
        }
#pragma unroll
        for (int kk = 0; kk < 16; kk++) {
            float4 a4 = *(const float4*)&As[cur][kk][ty*4];
            float b0 = Bs[cur][kk][tx*2], b1 = Bs[cur][kk][tx*2+1];
            float ar[4] = {a4.x, a4.y, a4.z, a4.w};
            int lane = kk & 7;
#pragma unroll
            for (int i = 0; i < 4; i++) {
                acc[i][0][lane] = __fmaf_rn(ar[i], b0, acc[i][0][lane]);
                acc[i][1][lane] = __fmaf_rn(ar[i], b1, acc[i][1][lane]);
            }
        }
        if (has) {
            int nxt = cur ^ 1;
            As[nxt][ak+0][am] = av.x; As[nxt][ak+1][am] = av.y;
            As[nxt][ak+2][am] = av.z; As[nxt][ak+3][am] = av.w;
            Bs[nxt][bk][bp + 0] = bb0;
            Bs[nxt][bk][bp + 1] = bb1;
            __syncthreads();
            cur = nxt;
        }
    }

#pragma unroll
    for (int i = 0; i < 4; i++) {
        int o = ty*4 + i;
        float bv = g_bh[o];
#pragma unroll
        for (int j = 0; j < 2; j++) {
            int p = p0 + tx*2 + j;
            if (p < HW) {
                float v = __fadd_rn(tree8(acc[i][j]), bv);
                if (o < 36)       out[O_LOC   + (size_t)n*90000 + (size_t)p*36 + o] = v;
                else if (o < 54)  out[O_SCORE + (size_t)n*45000 + (size_t)p*18 + (o-36)] = v;
            }
        }
    }
}

// ---------------- decode: softmax fg, anchors, loc2box, clip, keys ----------------
__global__ __launch_bounds__(256) void decode_kernel(
        float* __restrict__ out, const int* __restrict__ p_h, const int* __restrict__ p_w) {
    int g = blockIdx.x * blockDim.x + threadIdx.x;
    if (g >= N_IMG * NSORT) return;
    int n = g >> 15;
    int r = g & (NSORT - 1);
    if (r >= R_TOT) { g_keys[g] = ~0ULL; return; }

    int p = r / 9, a = r - (r/9)*9;
    const float* sc = out + O_SCORE + (size_t)n*45000 + (size_t)p*18 + 2*a;
    float s0 = sc[0], s1 = sc[1];
    float mx = fmaxf(s0, s1);
    float e0 = __nv_expf(__fsub_rn(s0, mx));
    float e1 = __nv_expf(__fsub_rn(s1, mx));
    float fg = __fdiv_rn(e1, __fadd_rn(e0, e1));

    int ridx = a / 3, sidx = a - ridx*3;
    double rr = (ridx == 0) ? 0.5 : ((ridx == 1) ? 1.0 : 2.0);
    double ss = (sidx == 0) ? 8.0 : ((sidx == 1) ? 16.0 : 32.0);
    double hh = (16.0 * sqrt(rr)) * ss;
    double wwd = (16.0 * sqrt(1.0 / rr)) * ss;
    float base0 = (float)(8.0 - hh * 0.5);
    float base1 = (float)(8.0 - wwd * 0.5);
    float base2 = (float)(8.0 + hh * 0.5);
    float base3 = (float)(8.0 + wwd * 0.5);
    int py = p / 50, px = p - (p/50)*50;
    double shy = (double)(16 * py);
    double shx = (double)(16 * px);
    float a0 = (float)(shy + (double)base0);
    float a1 = (float)(shx + (double)base1);
    float a2 = (float)(shy + (double)base2);
    float a3 = (float)(shx + (double)base3);
    if (n == 0) {
        float* ao = out + O_ANCH + (size_t)r * 4;
        ao[0] = a0; ao[1] = a1; ao[2] = a2; ao[3] = a3;
    }

    const float* lp = out + O_LOC + (size_t)n*90000 + (size_t)p*36 + a*4;
    float l0 = lp[0], l1 = lp[1], l2 = lp[2], l3 = lp[3];
    float ah = __fsub_rn(a2, a0);
    float aw = __fsub_rn(a3, a1);
    float acy = __fadd_rn(a0, __fmul_rn(0.5f, ah));
    float acx = __fadd_rn(a1, __fmul_rn(0.5f, aw));
    float bcy = __fadd_rn(__fmul_rn(l0, ah), acy);
    float bcx = __fadd_rn(__fmul_rn(l1, aw), acx);
    float bh = __fmul_rn(__nv_expf(l2), ah);
    float bw = __fmul_rn(__nv_expf(l3), aw);
    float y1 = __fsub_rn(bcy, __fmul_rn(0.5f, bh));
    float x1 = __fsub_rn(bcx, __fmul_rn(0.5f, bw));
    float y2 = __fadd_rn(bcy, __fmul_rn(0.5f, bh));
    float x2 = __fadd_rn(bcx, __fmul_rn(0.5f, bw));
    float H = (float)(*p_h), W = (float)(*p_w);
    y1 = fminf(fmaxf(y1, 0.f), H); x1 = fminf(fmaxf(x1, 0.f), W);
    y2 = fminf(fmaxf(y2, 0.f), H); x2 = fminf(fmaxf(x2, 0.f), W);
    bool valid = (__fsub_rn(y2, y1) >= 16.0f) && (__fsub_rn(x2, x1) >= 16.0f);
    float score = valid ? fg : -INFINITY;

    g_roi[(size_t)n * R_TOT + r] = make_float4(y1, x1, y2, x2);

    unsigned ub = __float_as_uint(score);
    unsigned s = (ub & 0x80000000u) ? ~ub : (ub | 0x80000000u);
    g_keys[g] = ((unsigned long long)(~s) << 32) | (unsigned)r;
}

// ---------------- bitonic sort ----------------
__device__ __forceinline__ void cmpswap(unsigned long long& a, unsigned long long& b, bool up) {
    bool sw = up ? (a > b) : (a < b);
    if (sw) { unsigned long long t = a; a = b; b = t; }
}

__global__ __launch_bounds__(1024, 1) void bitonic_local_kernel() {
    __shared__ unsigned long long sk[2048];
    int n = blockIdx.x >> 4;
    int chunk = blockIdx.x & 15;
    int base = n * NSORT + chunk * 2048;
    int t = threadIdx.x;
    sk[t] = g_keys[base + t];
    sk[t + 1024] = g_keys[base + t + 1024];
    __syncthreads();
    int gb = chunk * 2048;
    for (int k = 2; k <= 2048; k <<= 1) {
        for (int j = k >> 1; j > 0; j >>= 1) {
            int lo = ((t & ~(j - 1)) << 1) | (t & (j - 1));
            int hi = lo + j;
            bool up = (((gb + lo) & k) == 0);
            cmpswap(sk[lo], sk[hi], up);
            __syncthreads();
        }
    }
    g_keys[base + t] = sk[t];
    g_keys[base + t + 1024] = sk[t + 1024];
}

__global__ __launch_bounds__(256) void bitonic_global_kernel(int k, int j) {
    int g = blockIdx.x * blockDim.x + threadIdx.x;
    int n = g >> 14;
    int i = g & 16383;
    int lo = ((i & ~(j - 1)) << 1) | (i & (j - 1));
    int hi = lo + j;
    bool up = ((lo & k) == 0);
    unsigned long long* kp = g_keys + (size_t)n * NSORT;
    unsigned long long a = kp[lo], b = kp[hi];
    bool sw = up ? (a > b) : (a < b);
    if (sw) { kp[lo] = b; kp[hi] = a; }
}

__global__ __launch_bounds__(1024, 1) void bitonic_merge_kernel(int k) {
    __shared__ unsigned long long sk[2048];
    int n = blockIdx.x >> 4;
    int chunk = blockIdx.x & 15;
    int base = n * NSORT + chunk * 2048;
    int t = threadIdx.x;
    sk[t] = g_keys[base + t];
    sk[t + 1024] = g_keys[base + t + 1024];
    __syncthreads();
    bool up = (((chunk * 2048) & k) == 0);
    for (int j = 1024; j > 0; j >>= 1) {
        int lo = ((t & ~(j - 1)) << 1) | (t & (j - 1));
        int hi = lo + j;
        cmpswap(sk[lo], sk[hi], up);
        __syncthreads();
    }
    g_keys[base + t] = sk[t];
    g_keys[base + t + 1024] = sk[t + 1024];
}

// ---------------- NMS ----------------
#define NMS_SMEM (NPROP*16 + NKEEP*5*4 + NPROP)

__global__ __launch_bounds__(128) void nms_kernel(float* __restrict__ out) {
    extern __shared__ char smem[];
    float4* sbox = (float4*)smem;
    float* skept = (float*)(smem + NPROP * 16);
    unsigned char* sfin = (unsigned char*)(smem + NPROP * 16 + NKEEP * 5 * 4);
    __shared__ int s_count;

    int n = blockIdx.x;
    int t = threadIdx.x;

    for (int r = t; r < NPROP; r += blockDim.x) {
        unsigned long long key = g_keys[(size_t)n * NSORT + r];
        unsigned idx = (unsigned)key;
        sbox[r] = g_roi[(size_t)n * R_TOT + idx];
        sfin[r] = ((unsigned)(key >> 32) != 0xFF800000u) ? 1 : 0;
    }
    __syncthreads();

    if (t < 32) {
        int count = 0;
        for (int i = 0; i < NPROP && count < NKEEP; i++) {
            if (!sfin[i]) continue;
            float4 bi = sbox[i];
            float areai = __fmul_rn(__fsub_rn(bi.z, bi.x), __fsub_rn(bi.w, bi.y));
            bool sup = false;
            for (int g0 = 0; g0 < count; g0 += 32) {
                int kk = g0 + t;
                bool pr = false;
                if (kk < count) {
                    const float* kb = &skept[kk * 5];
                    float ty_ = fmaxf(bi.x, kb[0]);
                    float tx_ = fmaxf(bi.y, kb[1]);
                    float by_ = fminf(bi.z, kb[2]);
                    float bx_ = fminf(bi.w, kb[3]);
                    float ih = fmaxf(__fsub_rn(by_, ty_), 0.f);
                    float iw = fmaxf(__fsub_rn(bx_, tx_), 0.f);
                    float inter = __fmul_rn(ih, iw);
                    float denom = __fadd_rn(__fsub_rn(__fadd_rn(areai, kb[4]), inter), 1e-9f);
                    float iou = __fdiv_rn(inter, denom);
                    pr = iou > 0.7f;
                }
                if (__ballot_sync(0xFFFFFFFFu, pr)) { sup = true; break; }
            }
            if (!sup) {
                if (t == 0) {
                    float* kb = &skept[count * 5];
                    kb[0] = bi.x; kb[1] = bi.y; kb[2] = bi.z; kb[3] = bi.w; kb[4] = areai;
                    float* o = out + O_ROIS + ((size_t)n * NKEEP + count) * 4;
                    o[0] = bi.x; o[1] = bi.y; o[2] = bi.z; o[3] = bi.w;
                }
                count++;
                __syncwarp();
            }
        }
        if (t == 0) s_count = count;
    }
    __syncthreads();
    int cnt = s_count;
    for (int r = t; r < NKEEP; r += blockDim.x) {
        if (r >= cnt) {
            float* o = out + O_ROIS + ((size_t)n * NKEEP + r) * 4;
            o[0] = 0.f; o[1] = 0.f; o[2] = 0.f; o[3] = 0.f;
        }
        out[O_RIDX + (size_t)n * NKEEP + r] = (float)n;
    }
}

// ---------------- launch (single stream) ----------------
extern "C" void kernel_launch(void* const* d_in, const int* in_sizes, int n_in,
                              void* d_out, int out_size) {
    const float* x       = (const float*)d_in[0];
    const float* w1      = (const float*)d_in[1];
    const float* b1      = (const float*)d_in[2];
    const float* w_score = (const float*)d_in[3];
    const float* b_score = (const float*)d_in[4];
    const float* w_loc   = (const float*)d_in[5];
    const float* b_loc   = (const float*)d_in[6];
    const int*   p_h     = (const int*)d_in[7];
    const int*   p_w     = (const int*)d_in[8];
    float* out = (float*)d_out;

    static int smem_set = 0;
    if (!smem_set) {
        cudaFuncSetAttribute(nms_kernel, cudaFuncAttributeMaxDynamicSharedMemorySize, NMS_SMEM);
        smem_set = 1;
    }

    prepack_kernel<<<(64*512 + 255)/256, 256>>>(w_score, b_score, w_loc, b_loc);

    dim3 gconv(79, 8, N_IMG);
    conv3x3_kernel<<<gconv, 128>>>(x, w1, b1);

    dim3 ghead(79, 1, N_IMG);
    heads_kernel<<<ghead, 256>>>(out);

    decode_kernel<<<(N_IMG * NSORT + 255)/256, 256>>>(out, p_h, p_w);

    bitonic_local_kernel<<<64, 1024>>>();
    for (int k = 4096; k <= NSORT; k <<= 1) {
        for (int j = k >> 1; j >= 2048; j >>= 1)
            bitonic_global_kernel<<<256, 256>>>(k, j);
        bitonic_merge_kernel<<<64, 1024>>>(k);
    }

    nms_kernel<<<N_IMG, 128, NMS_SMEM>>>(out);
}

// round 17
// speedup vs baseline: 1.0485x; 1.0012x over previous
#include <cuda_runtime.h>
#include <math.h>

#define N_IMG 4
#define CIN 512
#define COUT 512
#define HW 2500
#define KDIM (CIN*9)
#define R_TOT 22500
#define NSORT 32768
#define NPROP 6000
#define NKEEP 300

// output region offsets (floats)
#define O_LOC   0
#define O_SCORE 360000
#define O_ROIS  540000
#define O_RIDX  544800
#define O_ANCH  546000

extern "C" __device__ float __nv_expf(float);

// ---------------- scratch (static device arrays; no allocation) ----------------
__device__ __align__(16) float g_inter[N_IMG*COUT*HW];     // 20.48 MB
__device__ __align__(16) float g_wh[64*512];               // packed head weights
__device__ float g_bh[64];
__device__ __align__(16) float4 g_roi[N_IMG*R_TOT];        // clipped boxes
__device__ unsigned long long g_keys[N_IMG*NSORT];         // sort keys

// ---------------- prepack head weights ----------------
__global__ __launch_bounds__(256) void prepack_kernel(
        const float* __restrict__ w_score, const float* __restrict__ b_score,
        const float* __restrict__ w_loc,   const float* __restrict__ b_loc) {
    int i = blockIdx.x * blockDim.x + threadIdx.x;
    if (i < 64*512) {
        int o = i >> 9, c = i & 511;
        float v = 0.f;
        if (o < 36)      v = w_loc[o*512 + c];
        else if (o < 54) v = w_score[(o-36)*512 + c];
        g_wh[i] = v;
    }
    if (i < 64) {
        float v = 0.f;
        if (i < 36)      v = b_loc[i];
        else if (i < 54) v = b_score[i-36];
        g_bh[i] = v;
    }
}

// 8-lane pairwise-tree combine (DO NOT CHANGE — bit-exact contract with reference)
__device__ __forceinline__ float tree8(const float* l) {
    float s01 = __fadd_rn(l[0], l[1]);
    float s23 = __fadd_rn(l[2], l[3]);
    float s45 = __fadd_rn(l[4], l[5]);
    float s67 = __fadd_rn(l[6], l[7]);
    float a = __fadd_rn(s01, s23);
    float b = __fadd_rn(s45, s67);
    return __fadd_rn(a, b);
}

// ---------------- conv3x3 + bias + relu (implicit GEMM, 8-lane accumulation) ----------------
// BIT-EXACT CONTRACT: per output, k = c*9 + off ascending, lane = k & 7,
// __fmaf_rn chain per lane, tree8 combine, __fadd_rn bias, relu.
// R14 config: tile 64(M) x 32(P), 128 threads, microtile 4x4 x 8 lanes,
// double-buffered, K-tile 16, 2 CTAs/SM. Bs committed via float4 (conflict-free STS.128).
// grid: (79, 8, 4), block 128
__global__ __launch_bounds__(128, 2) void conv3x3_kernel(
        const float* __restrict__ x, const float* __restrict__ w,
        const float* __restrict__ bias) {
    const int n = blockIdx.z, mt = blockIdx.y, pt = blockIdx.x;
    const int tid = threadIdx.x;
    const int tx = tid & 7, ty = tid >> 3;     // tx 0..7 (p), ty 0..15 (m)
    __shared__ float As[2][16][68];
    __shared__ __align__(16) float Bs[2][16][36];
    const int m0 = mt * 64, p0 = pt * 32;
    float acc[4][4][8];
#pragma unroll
    for (int i = 0; i < 4; i++)
#pragma unroll
        for (int j = 0; j < 4; j++)
#pragma unroll
            for (int u = 0; u < 8; u++) acc[i][j][u] = 0.f;

    const float* xn = x + (size_t)n * CIN * HW;
    const int am = tid >> 1;          // 0..63
    const int ak = (tid & 1) * 8;     // 0 or 8
    const int bk = tid >> 3;          // 0..15
    const int bp = (tid & 7) * 4;     // 0..28
    const int pg0 = p0 + bp;

    const float* wrow = w + (size_t)(m0 + am) * KDIM;

    // ---- prologue: tile kt=0 into buffer 0 ----
    {
        float4 av0 = *(const float4*)(wrow + ak);
        float4 av1 = *(const float4*)(wrow + ak + 4);
        As[0][ak+0][am] = av0.x; As[0][ak+1][am] = av0.y;
        As[0][ak+2][am] = av0.z; As[0][ak+3][am] = av0.w;
        As[0][ak+4][am] = av1.x; As[0][ak+5][am] = av1.y;
        As[0][ak+6][am] = av1.z; As[0][ak+7][am] = av1.w;
        int k = bk;
        int c = k / 9;
        int off = k - c * 9;
        int dy = off / 3 - 1, dx = off - (off/3)*3 - 1;
        const float* xc = xn + (size_t)c * HW;
        float4 bv;
        float tmp[4];
#pragma unroll
        for (int j = 0; j < 4; j++) {
            int p = pg0 + j;
            float v = 0.f;
            if (p < HW) {
                int yy = p / 50 + dy, xx = p - (p/50)*50 + dx;
                if ((unsigned)yy < 50u && (unsigned)xx < 50u) v = xc[yy*50 + xx];
            }
            tmp[j] = v;
        }
        bv.x = tmp[0]; bv.y = tmp[1]; bv.z = tmp[2]; bv.w = tmp[3];
        *(float4*)&Bs[0][bk][bp] = bv;
    }
    __syncthreads();

    int cur = 0;
    for (int kt = 0; kt < KDIM; kt += 16) {
        const bool has = (kt + 16) < KDIM;
        float4 av0, av1;
        float bb[4];
        if (has) {
            const float* wn = wrow + kt + 16;
            av0 = *(const float4*)(wn + ak);
            av1 = *(const float4*)(wn + ak + 4);
            int k = kt + 16 + bk;
            int c = k / 9;
            int off = k - c * 9;
            int dy = off / 3 - 1, dx = off - (off/3)*3 - 1;
            const float* xc = xn + (size_t)c * HW;
#pragma unroll
            for (int j = 0; j < 4; j++) {
                bb[j] = 0.f;
                int p = pg0 + j;
                if (p < HW) {
                    int yy = p / 50 + dy, xx = p - (p/50)*50 + dx;
                    if ((unsigned)yy < 50u && (unsigned)xx < 50u) bb[j] = xc[yy*50 + xx];
                }
            }
        }
        // compute on buffer cur — IDENTICAL per-output operand order
#pragma unroll
        for (int kk = 0; kk < 16; kk++) {
            float4 a4 = *(const float4*)&As[cur][kk][ty*4];
            float4 b4 = *(const float4*)&Bs[cur][kk][tx*4];
            float ar[4] = {a4.x, a4.y, a4.z, a4.w};
            float br[4] = {b4.x, b4.y, b4.z, b4.w};
            int lane = kk & 7;
#pragma unroll
            for (int i = 0; i < 4; i++)
#pragma unroll
                for (int j = 0; j < 4; j++)
                    acc[i][j][lane] = __fmaf_rn(ar[i], br[j], acc[i][j][lane]);
        }
        if (has) {
            int nxt = cur ^ 1;
            As[nxt][ak+0][am] = av0.x; As[nxt][ak+1][am] = av0.y;
            As[nxt][ak+2][am] = av0.z; As[nxt][ak+3][am] = av0.w;
            As[nxt][ak+4][am] = av1.x; As[nxt][ak+5][am] = av1.y;
            As[nxt][ak+6][am] = av1.z; As[nxt][ak+7][am] = av1.w;
            float4 bv;
            bv.x = bb[0]; bv.y = bb[1]; bv.z = bb[2]; bv.w = bb[3];
            *(float4*)&Bs[nxt][bk][bp] = bv;
            __syncthreads();
            cur = nxt;
        }
    }

    float* on = g_inter + (size_t)n * COUT * HW;
#pragma unroll
    for (int i = 0; i < 4; i++) {
        int m = m0 + ty*4 + i;
        float bv = bias[m];
#pragma unroll
        for (int j = 0; j < 4; j++) {
            int p = p0 + tx*4 + j;
            if (p < HW) {
                float v = __fadd_rn(tree8(acc[i][j]), bv);
                on[(size_t)m * HW + p] = v > 0.f ? v : 0.f;
            }
        }
    }
}

// ---------------- 1x1 heads GEMM (64 packed outs x 512, 8-lane accumulation) ----------------
// Double-buffered; Bs committed as float2. grid: (79, 1, 4), block 256
__global__ __launch_bounds__(256, 2) void heads_kernel(float* __restrict__ out) {
    const int n = blockIdx.z, pt = blockIdx.x;
    const int tid = threadIdx.x;
    const int tx = tid & 15, ty = tid >> 4;
    __shared__ float As[2][16][68];
    __shared__ __align__(8) float Bs[2][16][36];
    const int p0 = pt * 32;
    float acc[4][2][8];
#pragma unroll
    for (int i = 0; i < 4; i++)
#pragma unroll
        for (int j = 0; j < 2; j++)
#pragma unroll
            for (int u = 0; u < 8; u++) acc[i][j][u] = 0.f;

    const float* bn = g_inter + (size_t)n * CIN * HW;
    const int am = tid >> 2, ak = (tid & 3) * 4;
    const int bk = tid >> 4, bp = (tid & 15) * 2;
    const int pgA = p0 + bp, pgB = p0 + bp + 1;
    const bool pvA = pgA < HW, pvB = pgB < HW;

    // prologue: kt=0
    {
        float4 av = *(const float4*)(g_wh + (size_t)am * 512 + ak);
        As[0][ak+0][am] = av.x; As[0][ak+1][am] = av.y;
        As[0][ak+2][am] = av.z; As[0][ak+3][am] = av.w;
        const float* brow = bn + (size_t)bk * HW;
        float2 bv;
        bv.x = pvA ? brow[pgA] : 0.f;
        bv.y = pvB ? brow[pgB] : 0.f;
        *(float2*)&Bs[0][bk][bp] = bv;
    }
    __syncthreads();

    int cur = 0;
    for (int kt = 0; kt < 512; kt += 16) {
        const bool has = (kt + 16) < 512;
        float4 av;
        float bb0 = 0.f, bb1 = 0.f;
        if (has) {
            av = *(const float4*)(g_wh + (size_t)am * 512 + (kt + 16) + ak);
            const float* brow = bn + (size_t)(kt + 16 + bk) * HW;
            if (pvA) bb0 = brow[pgA];
            if (pvB) bb1 = brow[pgB];
        }
#pragma unroll
        for (int kk = 0; kk < 16; kk++) {
            float4 a4 = *(const float4*)&As[cur][kk][ty*4];
            float b0 = Bs[cur][kk][tx*2], b1 = Bs[cur][kk][tx*2+1];
            float ar[4] = {a4.x, a4.y, a4.z, a4.w};
            int lane = kk & 7;
#pragma unroll
            for (int i = 0; i < 4; i++) {
                acc[i][0][lane] = __fmaf_rn(ar[i], b0, acc[i][0][lane]);
                acc[i][1][lane] = __fmaf_rn(ar[i], b1, acc[i][1][lane]);
            }
        }
        if (has) {
            int nxt = cur ^ 1;
            As[nxt][ak+0][am] = av.x; As[nxt][ak+1][am] = av.y;
            As[nxt][ak+2][am] = av.z; As[nxt][ak+3][am] = av.w;
            float2 bv; bv.x = bb0; bv.y = bb1;
            *(float2*)&Bs[nxt][bk][bp] = bv;
            __syncthreads();
            cur = nxt;
        }
    }

#pragma unroll
    for (int i = 0; i < 4; i++) {
        int o = ty*4 + i;
        float bv = g_bh[o];
#pragma unroll
        for (int j = 0; j < 2; j++) {
            int p = p0 + tx*2 + j;
            if (p < HW) {
                float v = __fadd_rn(tree8(acc[i][j]), bv);
                if (o < 36)       out[O_LOC   + (size_t)n*90000 + (size_t)p*36 + o] = v;
                else if (o < 54)  out[O_SCORE + (size_t)n*45000 + (size_t)p*18 + (o-36)] = v;
            }
        }
    }
}

// ---------------- decode: softmax fg, anchors, loc2box, clip, keys ----------------
__global__ __launch_bounds__(256) void decode_kernel(
        float* __restrict__ out, const int* __restrict__ p_h, const int* __restrict__ p_w) {
    int g = blockIdx.x * blockDim.x + threadIdx.x;
    if (g >= N_IMG * NSORT) return;
    int n = g >> 15;
    int r = g & (NSORT - 1);
    if (r >= R_TOT) { g_keys[g] = ~0ULL; return; }

    int p = r / 9, a = r - (r/9)*9;
    const float* sc = out + O_SCORE + (size_t)n*45000 + (size_t)p*18 + 2*a;
    float s0 = sc[0], s1 = sc[1];
    float mx = fmaxf(s0, s1);
    float e0 = __nv_expf(__fsub_rn(s0, mx));
    float e1 = __nv_expf(__fsub_rn(s1, mx));
    float fg = __fdiv_rn(e1, __fadd_rn(e0, e1));

    int ridx = a / 3, sidx = a - ridx*3;
    double rr = (ridx == 0) ? 0.5 : ((ridx == 1) ? 1.0 : 2.0);
    double ss = (sidx == 0) ? 8.0 : ((sidx == 1) ? 16.0 : 32.0);
    double hh = (16.0 * sqrt(rr)) * ss;
    double wwd = (16.0 * sqrt(1.0 / rr)) * ss;
    float base0 = (float)(8.0 - hh * 0.5);
    float base1 = (float)(8.0 - wwd * 0.5);
    float base2 = (float)(8.0 + hh * 0.5);
    float base3 = (float)(8.0 + wwd * 0.5);
    int py = p / 50, px = p - (p/50)*50;
    double shy = (double)(16 * py);
    double shx = (double)(16 * px);
    float a0 = (float)(shy + (double)base0);
    float a1 = (float)(shx + (double)base1);
    float a2 = (float)(shy + (double)base2);
    float a3 = (float)(shx + (double)base3);
    if (n == 0) {
        float* ao = out + O_ANCH + (size_t)r * 4;
        ao[0] = a0; ao[1] = a1; ao[2] = a2; ao[3] = a3;
    }

    const float* lp = out + O_LOC + (size_t)n*90000 + (size_t)p*36 + a*4;
    float l0 = lp[0], l1 = lp[1], l2 = lp[2], l3 = lp[3];
    float ah = __fsub_rn(a2, a0);
    float aw = __fsub_rn(a3, a1);
    float acy = __fadd_rn(a0, __fmul_rn(0.5f, ah));
    float acx = __fadd_rn(a1, __fmul_rn(0.5f, aw));
    float bcy = __fadd_rn(__fmul_rn(l0, ah), acy);
    float bcx = __fadd_rn(__fmul_rn(l1, aw), acx);
    float bh = __fmul_rn(__nv_expf(l2), ah);
    float bw = __fmul_rn(__nv_expf(l3), aw);
    float y1 = __fsub_rn(bcy, __fmul_rn(0.5f, bh));
    float x1 = __fsub_rn(bcx, __fmul_rn(0.5f, bw));
    float y2 = __fadd_rn(bcy, __fmul_rn(0.5f, bh));
    float x2 = __fadd_rn(bcx, __fmul_rn(0.5f, bw));
    float H = (float)(*p_h), W = (float)(*p_w);
    y1 = fminf(fmaxf(y1, 0.f), H); x1 = fminf(fmaxf(x1, 0.f), W);
    y2 = fminf(fmaxf(y2, 0.f), H); x2 = fminf(fmaxf(x2, 0.f), W);
    bool valid = (__fsub_rn(y2, y1) >= 16.0f) && (__fsub_rn(x2, x1) >= 16.0f);
    float score = valid ? fg : -INFINITY;

    g_roi[(size_t)n * R_TOT + r] = make_float4(y1, x1, y2, x2);

    unsigned ub = __float_as_uint(score);
    unsigned s = (ub & 0x80000000u) ? ~ub : (ub | 0x80000000u);
    g_keys[g] = ((unsigned long long)(~s) << 32) | (unsigned)r;
}

// ---------------- bitonic sort ----------------
__device__ __forceinline__ void cmpswap(unsigned long long& a, unsigned long long& b, bool up) {
    bool sw = up ? (a > b) : (a < b);
    if (sw) { unsigned long long t = a; a = b; b = t; }
}

__global__ __launch_bounds__(1024, 1) void bitonic_local_kernel() {
    __shared__ unsigned long long sk[2048];
    int n = blockIdx.x >> 4;
    int chunk = blockIdx.x & 15;
    int base = n * NSORT + chunk * 2048;
    int t = threadIdx.x;
    sk[t] = g_keys[base + t];
    sk[t + 1024] = g_keys[base + t + 1024];
    __syncthreads();
    int gb = chunk * 2048;
    for (int k = 2; k <= 2048; k <<= 1) {
        for (int j = k >> 1; j > 0; j >>= 1) {
            int lo = ((t & ~(j - 1)) << 1) | (t & (j - 1));
            int hi = lo + j;
            bool up = (((gb + lo) & k) == 0);
            cmpswap(sk[lo], sk[hi], up);
            __syncthreads();
        }
    }
    g_keys[base + t] = sk[t];
    g_keys[base + t + 1024] = sk[t + 1024];
}

// global step for (k, j) with j >= 4096. grid 256, block 256
__global__ __launch_bounds__(256) void bitonic_global_kernel(int k, int j) {
    int g = blockIdx.x * blockDim.x + threadIdx.x;
    int n = g >> 14;
    int i = g & 16383;
    int lo = ((i & ~(j - 1)) << 1) | (i & (j - 1));
    int hi = lo + j;
    bool up = ((lo & k) == 0);
    unsigned long long* kp = g_keys + (size_t)n * NSORT;
    unsigned long long a = kp[lo], b = kp[hi];
    bool sw = up ? (a > b) : (a < b);
    if (sw) { kp[lo] = b; kp[hi] = a; }
}

// 4096-wide merge: j = 2048..1 inside smem. Valid for k >= 4096
// (direction constant within each 4096-chunk). grid 32 (4 img x 8 chunks), block 1024.
__global__ __launch_bounds__(1024, 1) void bitonic_merge4k_kernel(int k) {
    __shared__ unsigned long long sk[4096];
    int n = blockIdx.x >> 3;
    int chunk = blockIdx.x & 7;
    int base = n * NSORT + chunk * 4096;
    int t = threadIdx.x;
    sk[t]        = g_keys[base + t];
    sk[t + 1024] = g_keys[base + t + 1024];
    sk[t + 2048] = g_keys[base + t + 2048];
    sk[t + 3072] = g_keys[base + t + 3072];
    __syncthreads();
    bool up = (((chunk * 4096) & k) == 0);   // constant per chunk since k >= 4096
    for (int j = 2048; j > 0; j >>= 1) {
#pragma unroll
        for (int e0 = 0; e0 < 2; e0++) {
            int e = t + e0 * 1024;           // 0..2047
            int lo = ((e & ~(j - 1)) << 1) | (e & (j - 1));
            int hi = lo + j;
            cmpswap(sk[lo], sk[hi], up);
        }
        __syncthreads();
    }
    g_keys[base + t]        = sk[t];
    g_keys[base + t + 1024] = sk[t + 1024];
    g_keys[base + t + 2048] = sk[t + 2048];
    g_keys[base + t + 3072] = sk[t + 3072];
}

// ---------------- NMS ----------------
#define NMS_SMEM (NPROP*16 + NKEEP*5*4 + NPROP)

__global__ __launch_bounds__(128) void nms_kernel(float* __restrict__ out) {
    extern __shared__ char smem[];
    float4* sbox = (float4*)smem;
    float* skept = (float*)(smem + NPROP * 16);
    unsigned char* sfin = (unsigned char*)(smem + NPROP * 16 + NKEEP * 5 * 4);
    __shared__ int s_count;

    int n = blockIdx.x;
    int t = threadIdx.x;

    for (int r = t; r < NPROP; r += blockDim.x) {
        unsigned long long key = g_keys[(size_t)n * NSORT + r];
        unsigned idx = (unsigned)key;
        sbox[r] = g_roi[(size_t)n * R_TOT + idx];
        sfin[r] = ((unsigned)(key >> 32) != 0xFF800000u) ? 1 : 0;
    }
    __syncthreads();

    if (t < 32) {
        int count = 0;
        for (int i = 0; i < NPROP && count < NKEEP; i++) {
            if (!sfin[i]) continue;
            float4 bi = sbox[i];
            float areai = __fmul_rn(__fsub_rn(bi.z, bi.x), __fsub_rn(bi.w, bi.y));
            bool sup = false;
            for (int g0 = 0; g0 < count; g0 += 32) {
                int kk = g0 + t;
                bool pr = false;
                if (kk < count) {
                    const float* kb = &skept[kk * 5];
                    float ty_ = fmaxf(bi.x, kb[0]);
                    float tx_ = fmaxf(bi.y, kb[1]);
                    float by_ = fminf(bi.z, kb[2]);
                    float bx_ = fminf(bi.w, kb[3]);
                    float ih = fmaxf(__fsub_rn(by_, ty_), 0.f);
                    float iw = fmaxf(__fsub_rn(bx_, tx_), 0.f);
                    float inter = __fmul_rn(ih, iw);
                    float denom = __fadd_rn(__fsub_rn(__fadd_rn(areai, kb[4]), inter), 1e-9f);
                    float iou = __fdiv_rn(inter, denom);
                    pr = iou > 0.7f;
                }
                if (__ballot_sync(0xFFFFFFFFu, pr)) { sup = true; break; }
            }
            if (!sup) {
                if (t == 0) {
                    float* kb = &skept[count * 5];
                    kb[0] = bi.x; kb[1] = bi.y; kb[2] = bi.z; kb[3] = bi.w; kb[4] = areai;
                    float* o = out + O_ROIS + ((size_t)n * NKEEP + count) * 4;
                    o[0] = bi.x; o[1] = bi.y; o[2] = bi.z; o[3] = bi.w;
                }
                count++;
                __syncwarp();
            }
        }
        if (t == 0) s_count = count;
    }
    __syncthreads();
    int cnt = s_count;
    for (int r = t; r < NKEEP; r += blockDim.x) {
        if (r >= cnt) {
            float* o = out + O_ROIS + ((size_t)n * NKEEP + r) * 4;
            o[0] = 0.f; o[1] = 0.f; o[2] = 0.f; o[3] = 0.f;
        }
        out[O_RIDX + (size_t)n * NKEEP + r] = (float)n;
    }
}

// ---------------- launch (single stream) ----------------
extern "C" void kernel_launch(void* const* d_in, const int* in_sizes, int n_in,
                              void* d_out, int out_size) {
    const float* x       = (const float*)d_in[0];
    const float* w1      = (const float*)d_in[1];
    const float* b1      = (const float*)d_in[2];
    const float* w_score = (const float*)d_in[3];
    const float* b_score = (const float*)d_in[4];
    const float* w_loc   = (const float*)d_in[5];
    const float* b_loc   = (const float*)d_in[6];
    const int*   p_h     = (const int*)d_in[7];
    const int*   p_w     = (const int*)d_in[8];
    float* out = (float*)d_out;

    static int smem_set = 0;
    if (!smem_set) {
        cudaFuncSetAttribute(nms_kernel, cudaFuncAttributeMaxDynamicSharedMemorySize, NMS_SMEM);
        smem_set = 1;
    }

    prepack_kernel<<<(64*512 + 255)/256, 256>>>(w_score, b_score, w_loc, b_loc);

    dim3 gconv(79, 8, N_IMG);
    conv3x3_kernel<<<gconv, 128>>>(x, w1, b1);

    dim3 ghead(79, 1, N_IMG);
    heads_kernel<<<ghead, 256>>>(out);

    decode_kernel<<<(N_IMG * NSORT + 255)/256, 256>>>(out, p_h, p_w);

    bitonic_local_kernel<<<64, 1024>>>();
    for (int k = 4096; k <= NSORT; k <<= 1) {
        for (int j = k >> 1; j >= 4096; j >>= 1)
            bitonic_global_kernel<<<256, 256>>>(k, j);
        bitonic_merge4k_kernel<<<32, 1024>>>(k);
    }

    nms_kernel<<<N_IMG, 128, NMS_SMEM>>>(out);
}